// round 5
// baseline (speedup 1.0000x reference)
#include <cuda_runtime.h>
#include <cuda_bf16.h>

// ---------------------------------------------------------------------------
// GCN 2-layer forward on GB300.
// CSR pull-aggregation (packed int2 edges) + packed-f32x2 GEMM with
// pre-duplicated B tile (no dup movs in inner loop).
// ---------------------------------------------------------------------------

#define MAX_N 50000
#define MAX_E 800000
#define DIM   128
#define SCAN_B 1024

typedef unsigned long long ull;

// scratch (device globals -- no allocation allowed)
__device__ int   g_deg  [MAX_N];
__device__ float g_dinv [MAX_N];
__device__ int   g_ptr  [MAX_N + 1];
__device__ int   g_cur  [MAX_N];
__device__ int   g_bsum [64];
__device__ int2  g_cedge[MAX_E];        // {src, float_as_int(norm)}
__device__ float g_h    [MAX_N * DIM];
__device__ float g_o1   [MAX_N * DIM];

// ---------------------------------------------------------------------------
__device__ __forceinline__ ull fma2(ull a, ull b, ull c) {
    ull d;
    asm("fma.rn.f32x2 %0, %1, %2, %3;" : "=l"(d) : "l"(a), "l"(b), "l"(c));
    return d;
}
__device__ __forceinline__ ull dup2(float x) {
    ull d;
    asm("mov.b64 %0, {%1, %1};" : "=l"(d) : "f"(x));
    return d;
}
__device__ __forceinline__ void unpack2(ull p, float& lo, float& hi) {
    asm("mov.b64 {%0, %1}, %2;" : "=f"(lo), "=f"(hi) : "l"(p));
}

// ---------------------------------------------------------------------------
__global__ void k_count(const int* __restrict__ dst, int* deg, int E) {
    int e = blockIdx.x * blockDim.x + threadIdx.x;
    if (e < E) atomicAdd(&deg[dst[e]], 1);
}

// exclusive scan of deg -> ptr (per-block) via shfl; emit block sums; dinv.
__global__ __launch_bounds__(SCAN_B) void k_scan1(const int* __restrict__ deg,
                                                  int* ptr, int* bsum,
                                                  float* dinv, int n) {
    __shared__ int ws[32];
    int t = threadIdx.x;
    int lane = t & 31, w = t >> 5;
    int i = blockIdx.x * SCAN_B + t;
    int v = (i < n) ? deg[i] : 0;
    if (i < n) dinv[i] = rsqrtf((float)(v + 1));

    // inclusive warp scan
    int x = v;
#pragma unroll
    for (int off = 1; off < 32; off <<= 1) {
        int y = __shfl_up_sync(0xFFFFFFFFu, x, off);
        if (lane >= off) x += y;
    }
    if (lane == 31) ws[w] = x;
    __syncthreads();
    if (w == 0) {
        int s = ws[lane];
#pragma unroll
        for (int off = 1; off < 32; off <<= 1) {
            int y = __shfl_up_sync(0xFFFFFFFFu, s, off);
            if (lane >= off) s += y;
        }
        ws[lane] = s;
    }
    __syncthreads();
    int incl = x + ((w > 0) ? ws[w - 1] : 0);
    if (i < n) ptr[i] = incl - v;                 // exclusive within block
    if (t == SCAN_B - 1) bsum[blockIdx.x] = incl;
}

// add block-prefix -> final ptr, init cur.
__global__ void k_scan3(int* ptr, const int* __restrict__ bsum, int* cur,
                        int n, int E, int nb) {
    __shared__ int spre[64];
    int t = threadIdx.x;
    if (t < 64) {
        int acc = 0;
        for (int b = 0; b < t && b < nb; b++) acc += bsum[b];
        spre[t] = acc;
    }
    __syncthreads();
    int i = blockIdx.x * blockDim.x + t;
    if (i < n) {
        int p = ptr[i] + spre[i / SCAN_B];
        ptr[i] = p;
        cur[i] = p;
    }
    if (i == 0) ptr[n] = E;
}

__global__ void k_fill(const int* __restrict__ src, const int* __restrict__ dst,
                       const float* __restrict__ dinv, int* cur,
                       int2* cedge, int E) {
    int e = blockIdx.x * blockDim.x + threadIdx.x;
    if (e >= E) return;
    int s = src[e], d = dst[e];
    int pos = atomicAdd(&cur[d], 1);
    int2 pr;
    pr.x = s;
    pr.y = __float_as_int(dinv[s] * dinv[d]);
    cedge[pos] = pr;                               // one 8B scattered store
}

// ---------------------------------------------------------------------------
// GEMM: C[M,128] = A[M,128] @ B[128,128]; BM=128, BK=8, 256 thr,
// 8x8 microtile as 4x8 packed f32x2 accumulators; B pre-duplicated in smem.
#define GBM 128
#define GBK 8

template <bool RELU>
__global__ __launch_bounds__(256) void k_gemm(const float* __restrict__ A,
                                              const float* __restrict__ B,
                                              float* __restrict__ C, int M) {
    __shared__ float As [GBK][GBM];   // transposed A tile: As[k][row]
    __shared__ ull   Bs2[GBK][DIM];   // pre-duplicated: Bs2[k][col] = {b,b}

    const int tid = threadIdx.x;
    const int m0  = blockIdx.x * GBM;
    const int ty  = tid >> 4;   // 0..15 row group
    const int tx  = tid & 15;   // 0..15 col group

    ull acc2[4][8];
#pragma unroll
    for (int ip = 0; ip < 4; ip++)
#pragma unroll
        for (int j = 0; j < 8; j++) acc2[ip][j] = 0ull;

    for (int k0 = 0; k0 < DIM; k0 += GBK) {
        {   // A tile 128x8 -> transposed: one float4 per thread
            int row = tid >> 1, c4 = tid & 1;
            float4 v = make_float4(0.f, 0.f, 0.f, 0.f);
            int gr = m0 + row;
            if (gr < M)
                v = *(const float4*)(A + (long)gr * DIM + k0 + c4 * 4);
            if (RELU) {
                v.x = fmaxf(v.x, 0.f); v.y = fmaxf(v.y, 0.f);
                v.z = fmaxf(v.z, 0.f); v.w = fmaxf(v.w, 0.f);
            }
            As[c4 * 4 + 0][row] = v.x;
            As[c4 * 4 + 1][row] = v.y;
            As[c4 * 4 + 2][row] = v.z;
            As[c4 * 4 + 3][row] = v.w;
        }
        {   // B tile 8x128, duplicated into f32x2: one float4 per thread
            int r = tid >> 5, c4 = tid & 31;
            float4 v = *(const float4*)(B + (long)(k0 + r) * DIM + c4 * 4);
            Bs2[r][c4 * 4 + 0] = dup2(v.x);
            Bs2[r][c4 * 4 + 1] = dup2(v.y);
            Bs2[r][c4 * 4 + 2] = dup2(v.z);
            Bs2[r][c4 * 4 + 3] = dup2(v.w);
        }
        __syncthreads();

#pragma unroll
        for (int k = 0; k < GBK; k++) {
            ulonglong2 aL  = *(const ulonglong2*)(&As [k][ty * 4]);
            ulonglong2 aH  = *(const ulonglong2*)(&As [k][ty * 4 + 64]);
            ulonglong2 b01 = *(const ulonglong2*)(&Bs2[k][tx * 4]);
            ulonglong2 b23 = *(const ulonglong2*)(&Bs2[k][tx * 4 + 2]);
            ulonglong2 b45 = *(const ulonglong2*)(&Bs2[k][tx * 4 + 64]);
            ulonglong2 b67 = *(const ulonglong2*)(&Bs2[k][tx * 4 + 66]);
            ull bd[8] = {b01.x, b01.y, b23.x, b23.y, b45.x, b45.y, b67.x, b67.y};
#pragma unroll
            for (int j = 0; j < 8; j++) {
                acc2[0][j] = fma2(aL.x, bd[j], acc2[0][j]);
                acc2[1][j] = fma2(aL.y, bd[j], acc2[1][j]);
                acc2[2][j] = fma2(aH.x, bd[j], acc2[2][j]);
                acc2[3][j] = fma2(aH.y, bd[j], acc2[3][j]);
            }
        }
        __syncthreads();
    }

#pragma unroll
    for (int ip = 0; ip < 4; ip++) {
        int baseRow = (ip < 2) ? (ty * 4 + 2 * ip) : (64 + ty * 4 + 2 * (ip - 2));
        float lo[8], hi[8];
#pragma unroll
        for (int j = 0; j < 8; j++) unpack2(acc2[ip][j], lo[j], hi[j]);
        int r0 = m0 + baseRow, r1 = r0 + 1;
        if (r0 < M) {
            *(float4*)(C + (long)r0 * DIM + tx * 4)      = make_float4(lo[0], lo[1], lo[2], lo[3]);
            *(float4*)(C + (long)r0 * DIM + tx * 4 + 64) = make_float4(lo[4], lo[5], lo[6], lo[7]);
        }
        if (r1 < M) {
            *(float4*)(C + (long)r1 * DIM + tx * 4)      = make_float4(hi[0], hi[1], hi[2], hi[3]);
            *(float4*)(C + (long)r1 * DIM + tx * 4 + 64) = make_float4(hi[4], hi[5], hi[6], hi[7]);
        }
    }
}

// ---------------------------------------------------------------------------
// pull-aggregation: warp per node, packed int2 edges.
__global__ __launch_bounds__(256) void k_agg(const float* __restrict__ h,
                                             const int* __restrict__ ptr,
                                             const int2* __restrict__ cedge,
                                             const float* __restrict__ dinv,
                                             const float* __restrict__ b,
                                             float* __restrict__ out, int n) {
    int node = (blockIdx.x * blockDim.x + threadIdx.x) >> 5;
    int lane = threadIdx.x & 31;
    if (node >= n) return;

    const float4* h4 = (const float4*)h;
    float di = dinv[node];
    float w0 = di * di;
    float4 hv = h4[(long)node * 32 + lane];
    float4 bv = ((const float4*)b)[lane];
    float4 acc;
    acc.x = hv.x * w0 + bv.x;
    acc.y = hv.y * w0 + bv.y;
    acc.z = hv.z * w0 + bv.z;
    acc.w = hv.w * w0 + bv.w;

    int beg = ptr[node], end = ptr[node + 1];
    int j = beg;
    for (; j + 3 < end; j += 4) {
        int2 e0 = cedge[j],     e1 = cedge[j + 1];
        int2 e2 = cedge[j + 2], e3 = cedge[j + 3];
        float n0 = __int_as_float(e0.y), n1 = __int_as_float(e1.y);
        float n2 = __int_as_float(e2.y), n3 = __int_as_float(e3.y);
        float4 v0 = h4[(long)e0.x * 32 + lane];
        float4 v1 = h4[(long)e1.x * 32 + lane];
        float4 v2 = h4[(long)e2.x * 32 + lane];
        float4 v3 = h4[(long)e3.x * 32 + lane];
        acc.x += v0.x * n0; acc.y += v0.y * n0; acc.z += v0.z * n0; acc.w += v0.w * n0;
        acc.x += v1.x * n1; acc.y += v1.y * n1; acc.z += v1.z * n1; acc.w += v1.w * n1;
        acc.x += v2.x * n2; acc.y += v2.y * n2; acc.z += v2.z * n2; acc.w += v2.w * n2;
        acc.x += v3.x * n3; acc.y += v3.y * n3; acc.z += v3.z * n3; acc.w += v3.w * n3;
    }
    for (; j < end; j++) {
        int2 e = cedge[j];
        float w = __int_as_float(e.y);
        float4 v = h4[(long)e.x * 32 + lane];
        acc.x += v.x * w; acc.y += v.y * w; acc.z += v.z * w; acc.w += v.w * w;
    }
    ((float4*)out)[(long)node * 32 + lane] = acc;
}

// ---------------------------------------------------------------------------
extern "C" void kernel_launch(void* const* d_in, const int* in_sizes, int n_in,
                              void* d_out, int out_size) {
    const float* x  = (const float*)d_in[0];
    const int*   ei = (const int*)  d_in[1];
    const float* W1 = (const float*)d_in[2];
    const float* b1 = (const float*)d_in[3];
    const float* W2 = (const float*)d_in[4];
    const float* b2 = (const float*)d_in[5];
    float* out = (float*)d_out;

    const int N = in_sizes[0] / DIM;
    const int E = in_sizes[1] / 2;
    const int* src = ei;
    const int* dst = ei + E;

    int *deg, *ptr, *cur, *bsum;
    int2* cedge;
    float *dinv, *h, *o1;
    cudaGetSymbolAddress((void**)&deg,   g_deg);
    cudaGetSymbolAddress((void**)&dinv,  g_dinv);
    cudaGetSymbolAddress((void**)&ptr,   g_ptr);
    cudaGetSymbolAddress((void**)&cur,   g_cur);
    cudaGetSymbolAddress((void**)&bsum,  g_bsum);
    cudaGetSymbolAddress((void**)&cedge, g_cedge);
    cudaGetSymbolAddress((void**)&h,     g_h);
    cudaGetSymbolAddress((void**)&o1,    g_o1);

    const int T = 256;
    const int nb_scan = (N + SCAN_B - 1) / SCAN_B;

    // ---- CSR + normalization build (shared by both layers) ----
    cudaMemsetAsync(deg, 0, (size_t)N * sizeof(int));
    k_count<<<(E + T - 1) / T, T>>>(dst, deg, E);
    k_scan1<<<nb_scan, SCAN_B>>>(deg, ptr, bsum, dinv, N);
    k_scan3<<<(N + T - 1) / T, T>>>(ptr, bsum, cur, N, E, nb_scan);
    k_fill <<<(E + T - 1) / T, T>>>(src, dst, dinv, cur, cedge, E);

    const int gemm_blocks = (N + GBM - 1) / GBM;
    const int agg_blocks  = (N * 32 + T - 1) / T;

    // ---- layer 1 ----
    k_gemm<false><<<gemm_blocks, 256>>>(x, W1, h, N);
    k_agg        <<<agg_blocks, T>>>(h, ptr, cedge, dinv, b1, o1, N);

    // ---- layer 2 ----
    k_gemm<true> <<<gemm_blocks, 256>>>(o1, W2, h, N);
    k_agg        <<<agg_blocks, T>>>(h, ptr, cedge, dinv, b2, out, N);
}

// round 6
// speedup vs baseline: 1.6526x; 1.6526x over previous
#include <cuda_runtime.h>
#include <cuda_bf16.h>

// ---------------------------------------------------------------------------
// GCN 2-layer forward on GB300.
// CSR pull-aggregation (packed int2 edges) + plain-FFMA tiled GEMM (BK=16).
// GEMM-1 runs on a forked stream, overlapped with the CSR build.
// ---------------------------------------------------------------------------

#define MAX_N 50000
#define MAX_E 800000
#define DIM   128
#define SCAN_B 1024

// scratch (device globals -- no allocation allowed)
__device__ int   g_deg  [MAX_N];
__device__ float g_dinv [MAX_N];
__device__ int   g_ptr  [MAX_N + 1];
__device__ int   g_cur  [MAX_N];
__device__ int   g_bsum [64];
__device__ int2  g_cedge[MAX_E];        // {src, float_as_int(norm)}
__device__ float g_h    [MAX_N * DIM];
__device__ float g_o1   [MAX_N * DIM];

// ---------------------------------------------------------------------------
__global__ void k_count(const int* __restrict__ dst, int* deg, int E) {
    int e = blockIdx.x * blockDim.x + threadIdx.x;
    if (e < E) atomicAdd(&deg[dst[e]], 1);
}

// exclusive scan of deg -> ptr (per-block) via shfl; emit block sums; dinv.
__global__ __launch_bounds__(SCAN_B) void k_scan1(const int* __restrict__ deg,
                                                  int* ptr, int* bsum,
                                                  float* dinv, int n) {
    __shared__ int ws[32];
    int t = threadIdx.x;
    int lane = t & 31, w = t >> 5;
    int i = blockIdx.x * SCAN_B + t;
    int v = (i < n) ? deg[i] : 0;
    if (i < n) dinv[i] = rsqrtf((float)(v + 1));

    int x = v;
#pragma unroll
    for (int off = 1; off < 32; off <<= 1) {
        int y = __shfl_up_sync(0xFFFFFFFFu, x, off);
        if (lane >= off) x += y;
    }
    if (lane == 31) ws[w] = x;
    __syncthreads();
    if (w == 0) {
        int s = ws[lane];
#pragma unroll
        for (int off = 1; off < 32; off <<= 1) {
            int y = __shfl_up_sync(0xFFFFFFFFu, s, off);
            if (lane >= off) s += y;
        }
        ws[lane] = s;
    }
    __syncthreads();
    int incl = x + ((w > 0) ? ws[w - 1] : 0);
    if (i < n) ptr[i] = incl - v;                 // exclusive within block
    if (t == SCAN_B - 1) bsum[blockIdx.x] = incl;
}

// add block-prefix -> final ptr, init cur.
__global__ void k_scan3(int* ptr, const int* __restrict__ bsum, int* cur,
                        int n, int E, int nb) {
    __shared__ int spre[64];
    int t = threadIdx.x;
    if (t < 64) {
        int acc = 0;
        for (int b = 0; b < t && b < nb; b++) acc += bsum[b];
        spre[t] = acc;
    }
    __syncthreads();
    int i = blockIdx.x * blockDim.x + t;
    if (i < n) {
        int p = ptr[i] + spre[i / SCAN_B];
        ptr[i] = p;
        cur[i] = p;
    }
    if (i == 0) ptr[n] = E;
}

__global__ void k_fill(const int* __restrict__ src, const int* __restrict__ dst,
                       const float* __restrict__ dinv, int* cur,
                       int2* cedge, int E) {
    int e = blockIdx.x * blockDim.x + threadIdx.x;
    if (e >= E) return;
    int s = src[e], d = dst[e];
    int pos = atomicAdd(&cur[d], 1);
    int2 pr;
    pr.x = s;
    pr.y = __float_as_int(dinv[s] * dinv[d]);
    cedge[pos] = pr;
}

// ---------------------------------------------------------------------------
// GEMM: C[M,128] = A[M,128] @ B[128,128]; BM=128, BK=16, 256 thr, 8x8 microtile,
// plain FFMA (known-good round-2 inner loop, half the sync count).
#define GBM 128
#define GBK 16

template <bool RELU>
__global__ __launch_bounds__(256) void k_gemm(const float* __restrict__ A,
                                              const float* __restrict__ B,
                                              float* __restrict__ C, int M) {
    __shared__ float As[GBK][GBM];   // transposed A tile: As[k][row]
    __shared__ float Bs[GBK][DIM];

    const int tid = threadIdx.x;
    const int m0  = blockIdx.x * GBM;
    const int ty  = tid >> 4;   // 0..15 row group
    const int tx  = tid & 15;   // 0..15 col group

    float acc[8][8];
#pragma unroll
    for (int i = 0; i < 8; i++)
#pragma unroll
        for (int j = 0; j < 8; j++) acc[i][j] = 0.0f;

    for (int k0 = 0; k0 < DIM; k0 += GBK) {
        {   // A tile 128x16 -> transposed: two float4 per thread
            int row = tid >> 1;              // 0..127
            int c8  = (tid & 1) * 8;         // 0 or 8
            int gr  = m0 + row;
#pragma unroll
            for (int t = 0; t < 2; t++) {
                float4 v = make_float4(0.f, 0.f, 0.f, 0.f);
                if (gr < M)
                    v = *(const float4*)(A + (long)gr * DIM + k0 + c8 + t * 4);
                if (RELU) {
                    v.x = fmaxf(v.x, 0.f); v.y = fmaxf(v.y, 0.f);
                    v.z = fmaxf(v.z, 0.f); v.w = fmaxf(v.w, 0.f);
                }
                As[c8 + t * 4 + 0][row] = v.x;
                As[c8 + t * 4 + 1][row] = v.y;
                As[c8 + t * 4 + 2][row] = v.z;
                As[c8 + t * 4 + 3][row] = v.w;
            }
        }
        {   // B tile 16x128: two float4 per thread
            int r   = tid >> 4;              // 0..15
            int c8  = (tid & 15) * 8;        // 0,8,...,120
#pragma unroll
            for (int t = 0; t < 2; t++)
                *(float4*)(&Bs[r][c8 + t * 4]) =
                    *(const float4*)(B + (long)(k0 + r) * DIM + c8 + t * 4);
        }
        __syncthreads();

#pragma unroll
        for (int k = 0; k < GBK; k++) {
            float a[8], b[8];
            *(float4*)(a)     = *(const float4*)(&As[k][ty * 4]);
            *(float4*)(a + 4) = *(const float4*)(&As[k][ty * 4 + 64]);
            *(float4*)(b)     = *(const float4*)(&Bs[k][tx * 4]);
            *(float4*)(b + 4) = *(const float4*)(&Bs[k][tx * 4 + 64]);
#pragma unroll
            for (int i = 0; i < 8; i++)
#pragma unroll
                for (int j = 0; j < 8; j++)
                    acc[i][j] += a[i] * b[j];
        }
        __syncthreads();
    }

#pragma unroll
    for (int i = 0; i < 8; i++) {
        int gr = m0 + ty * 4 + (i & 3) + (i >> 2) * 64;
        if (gr < M) {
            *(float4*)(C + (long)gr * DIM + tx * 4) =
                make_float4(acc[i][0], acc[i][1], acc[i][2], acc[i][3]);
            *(float4*)(C + (long)gr * DIM + tx * 4 + 64) =
                make_float4(acc[i][4], acc[i][5], acc[i][6], acc[i][7]);
        }
    }
}

// ---------------------------------------------------------------------------
// pull-aggregation: warp per node, packed int2 edges.
__global__ __launch_bounds__(256) void k_agg(const float* __restrict__ h,
                                             const int* __restrict__ ptr,
                                             const int2* __restrict__ cedge,
                                             const float* __restrict__ dinv,
                                             const float* __restrict__ b,
                                             float* __restrict__ out, int n) {
    int node = (blockIdx.x * blockDim.x + threadIdx.x) >> 5;
    int lane = threadIdx.x & 31;
    if (node >= n) return;

    const float4* h4 = (const float4*)h;
    float di = dinv[node];
    float w0 = di * di;
    float4 hv = h4[(long)node * 32 + lane];
    float4 bv = ((const float4*)b)[lane];
    float4 acc;
    acc.x = hv.x * w0 + bv.x;
    acc.y = hv.y * w0 + bv.y;
    acc.z = hv.z * w0 + bv.z;
    acc.w = hv.w * w0 + bv.w;

    int beg = ptr[node], end = ptr[node + 1];
    int j = beg;
    for (; j + 3 < end; j += 4) {
        int2 e0 = cedge[j],     e1 = cedge[j + 1];
        int2 e2 = cedge[j + 2], e3 = cedge[j + 3];
        float n0 = __int_as_float(e0.y), n1 = __int_as_float(e1.y);
        float n2 = __int_as_float(e2.y), n3 = __int_as_float(e3.y);
        float4 v0 = h4[(long)e0.x * 32 + lane];
        float4 v1 = h4[(long)e1.x * 32 + lane];
        float4 v2 = h4[(long)e2.x * 32 + lane];
        float4 v3 = h4[(long)e3.x * 32 + lane];
        acc.x += v0.x * n0; acc.y += v0.y * n0; acc.z += v0.z * n0; acc.w += v0.w * n0;
        acc.x += v1.x * n1; acc.y += v1.y * n1; acc.z += v1.z * n1; acc.w += v1.w * n1;
        acc.x += v2.x * n2; acc.y += v2.y * n2; acc.z += v2.z * n2; acc.w += v2.w * n2;
        acc.x += v3.x * n3; acc.y += v3.y * n3; acc.z += v3.z * n3; acc.w += v3.w * n3;
    }
    for (; j < end; j++) {
        int2 e = cedge[j];
        float w = __int_as_float(e.y);
        float4 v = h4[(long)e.x * 32 + lane];
        acc.x += v.x * w; acc.y += v.y * w; acc.z += v.z * w; acc.w += v.w * w;
    }
    ((float4*)out)[(long)node * 32 + lane] = acc;
}

// ---------------------------------------------------------------------------
extern "C" void kernel_launch(void* const* d_in, const int* in_sizes, int n_in,
                              void* d_out, int out_size) {
    const float* x  = (const float*)d_in[0];
    const int*   ei = (const int*)  d_in[1];
    const float* W1 = (const float*)d_in[2];
    const float* b1 = (const float*)d_in[3];
    const float* W2 = (const float*)d_in[4];
    const float* b2 = (const float*)d_in[5];
    float* out = (float*)d_out;

    const int N = in_sizes[0] / DIM;
    const int E = in_sizes[1] / 2;
    const int* src = ei;
    const int* dst = ei + E;

    int *deg, *ptr, *cur, *bsum;
    int2* cedge;
    float *dinv, *h, *o1;
    cudaGetSymbolAddress((void**)&deg,   g_deg);
    cudaGetSymbolAddress((void**)&dinv,  g_dinv);
    cudaGetSymbolAddress((void**)&ptr,   g_ptr);
    cudaGetSymbolAddress((void**)&cur,   g_cur);
    cudaGetSymbolAddress((void**)&bsum,  g_bsum);
    cudaGetSymbolAddress((void**)&cedge, g_cedge);
    cudaGetSymbolAddress((void**)&h,     g_h);
    cudaGetSymbolAddress((void**)&o1,    g_o1);

    const int T = 256;
    const int nb_scan    = (N + SCAN_B - 1) / SCAN_B;
    const int gemm_blocks = (N + GBM - 1) / GBM;
    const int agg_blocks  = (N * 32 + T - 1) / T;

    // Forked stream for GEMM-1 (independent of the CSR build).
    // Host-side handle creation only (no device memory); created per call,
    // not destroyed while capture is active.
    cudaStream_t s2;
    cudaStreamCreateWithFlags(&s2, cudaStreamNonBlocking);
    cudaEvent_t e_fork, e_join;
    cudaEventCreateWithFlags(&e_fork, cudaEventDisableTiming);
    cudaEventCreateWithFlags(&e_join, cudaEventDisableTiming);

    // fork: GEMM-1 on s2
    cudaEventRecord(e_fork, 0);
    cudaStreamWaitEvent(s2, e_fork, 0);
    k_gemm<false><<<gemm_blocks, 256, 0, s2>>>(x, W1, h, N);
    cudaEventRecord(e_join, s2);

    // CSR + normalization build on the main stream (overlapped with GEMM-1)
    cudaMemsetAsync(deg, 0, (size_t)N * sizeof(int));
    k_count<<<(E + T - 1) / T, T>>>(dst, deg, E);
    k_scan1<<<nb_scan, SCAN_B>>>(deg, ptr, bsum, dinv, N);
    k_scan3<<<(N + T - 1) / T, T>>>(ptr, bsum, cur, N, E, nb_scan);
    k_fill <<<(E + T - 1) / T, T>>>(src, dst, dinv, cur, cedge, E);

    // join: agg-1 needs both h (s2) and the CSR (main)
    cudaStreamWaitEvent(0, e_join, 0);
    k_agg<<<agg_blocks, T>>>(h, ptr, cedge, dinv, b1, o1, N);

    // ---- layer 2 ----
    k_gemm<true><<<gemm_blocks, 256>>>(o1, W2, h, N);
    k_agg       <<<agg_blocks, T>>>(h, ptr, cedge, dinv, b2, out, N);
}